// round 16
// baseline (speedup 1.0000x reference)
#include <cuda_runtime.h>
#include <cuda_fp16.h>
#include <cstdint>

// ===========================================================================
// mie_51281909514553 — 3-layer expert-merged MLP, pure fp16 HMMA
//   wn = weights/sum(weights); per layer: x = PReLU(x @ Wm + bm, a)
//   Weights + activations fp16 (RN), fp32 accumulate (HMMA ceiling:
//   512 MAC/cyc/SM measured). R16: dual-chain M-split pipeline with
//   DISTINCT activation buffers per layer (xh -> act0 -> act1) to remove
//   the cross-chain buffer-reuse race that R15 exposed.
// ===========================================================================

#define M_ROWS 8192
#define M_HALF 4096
#define E_EXPERTS 8

// ------------------------------ scratch (no allocs allowed) ----------------
__device__ __half g_xh[8192 * 512];        // L0 input (fp16)   — read-only after cast
__device__ __half g_a0[8192 * 1024];       // L0 out / L1 in
__device__ __half g_a1[8192 * 1024];       // L1 out / L2 in
__device__ __half g_wt0[1024 * 512];       // merged W^T: [N][K] fp16
__device__ __half g_wt1[1024 * 1024];
__device__ __half g_wt2[512 * 1024];
__device__ float g_bm0[1024];
__device__ float g_bm1[1024];
__device__ float g_bm2[512];

// ------------------------------ helpers ------------------------------------
__device__ __forceinline__ uint32_t smem_u32(const void* p) {
    uint32_t a;
    asm("{ .reg .u64 t; cvta.to.shared.u64 t, %1; cvt.u32.u64 %0, t; }"
        : "=r"(a) : "l"(p));
    return a;
}

__device__ __forceinline__ void cp16(uint32_t s, const void* g) {
    asm volatile("cp.async.cg.shared.global [%0], [%1], 16;" :: "r"(s), "l"(g) : "memory");
}
#define CP_COMMIT() asm volatile("cp.async.commit_group;" ::: "memory")
#define CP_WAIT(n)  asm volatile("cp.async.wait_group %0;" :: "n"(n) : "memory")

__device__ __forceinline__ void ldsm4(uint32_t& r0, uint32_t& r1,
                                      uint32_t& r2, uint32_t& r3, uint32_t a) {
    asm volatile("ldmatrix.sync.aligned.m8n8.x4.shared.b16 {%0,%1,%2,%3}, [%4];"
                 : "=r"(r0), "=r"(r1), "=r"(r2), "=r"(r3) : "r"(a));
}

__device__ __forceinline__ void mma_f16(float* c, const uint32_t* a, const uint32_t* b) {
    asm volatile(
        "mma.sync.aligned.m16n8k16.row.col.f32.f16.f16.f32 "
        "{%0,%1,%2,%3}, {%4,%5,%6,%7}, {%8,%9}, {%0,%1,%2,%3};"
        : "+f"(c[0]), "+f"(c[1]), "+f"(c[2]), "+f"(c[3])
        : "r"(a[0]), "r"(a[1]), "r"(a[2]), "r"(a[3]), "r"(b[0]), "r"(b[1]));
}

// ------------------------------ merge+transpose (R13 proven) ---------------
__global__ void merge_w(const float* __restrict__ weights,
                        const float* __restrict__ W,
                        const float* __restrict__ b,
                        __half* __restrict__ T,
                        float* __restrict__ bm,
                        int K, int N) {
    __shared__ float tile[32][33];
    const int tid = threadIdx.x;

    float s = 0.f;
#pragma unroll
    for (int e = 0; e < E_EXPERTS; e++) s += weights[e];
    const float inv = 1.f / s;
    float wn[E_EXPERTS];
#pragma unroll
    for (int e = 0; e < E_EXPERTS; e++) wn[e] = weights[e] * inv;

    const int k0 = blockIdx.x * 32, n0 = blockIdx.y * 32;
    const size_t KN = (size_t)K * N;

    {
        const int kk = tid >> 3;
        const int v = tid & 7;
        const float* src = W + (size_t)(k0 + kk) * N + n0 + v * 4;
        float4 acc = make_float4(0.f, 0.f, 0.f, 0.f);
#pragma unroll
        for (int e = 0; e < E_EXPERTS; e++) {
            float4 w4 = *reinterpret_cast<const float4*>(src + (size_t)e * KN);
            acc.x = fmaf(wn[e], w4.x, acc.x);
            acc.y = fmaf(wn[e], w4.y, acc.y);
            acc.z = fmaf(wn[e], w4.z, acc.z);
            acc.w = fmaf(wn[e], w4.w, acc.w);
        }
        tile[kk][v * 4 + 0] = acc.x;
        tile[kk][v * 4 + 1] = acc.y;
        tile[kk][v * 4 + 2] = acc.z;
        tile[kk][v * 4 + 3] = acc.w;
    }

    if (blockIdx.x == 0 && tid < 32) {
        const int n = n0 + tid;
        float acc = 0.f;
#pragma unroll
        for (int e = 0; e < E_EXPERTS; e++) acc += wn[e] * b[e * N + n];
        bm[n] = acc;
    }
    __syncthreads();

    {
        const int tx = tid & 31;
        for (int ty = tid >> 5; ty < 32; ty += 8)
            T[(size_t)(n0 + ty) * K + k0 + tx] = __float2half_rn(tile[tx][ty]);
    }
}

// fp32 -> fp16, vectorized (float4 in, half2x2 out)
__global__ void cast_x(const float4* __restrict__ x, __half2* __restrict__ xh, int n4) {
    int i = blockIdx.x * blockDim.x + threadIdx.x;
    if (i < n4) {
        float4 v = x[i];
        __half2 a, b;
        a.x = __float2half_rn(v.x); a.y = __float2half_rn(v.y);
        b.x = __float2half_rn(v.z); b.y = __float2half_rn(v.w);
        xh[2 * i] = a;
        xh[2 * i + 1] = b;
    }
}

// ------------------------------ HMMA GEMM ----------------------------------
// BM=128, BN=128, BK=32, 256 threads (8 warps: 4 M x 2 N), warp tile 32x64.
// 2-stage cp.async pipeline, one sync per chunk, 2 CTAs per SM.
#define BK 32
#define TSTRIDE 40
#define ROWB (TSTRIDE * 2)                  // 80 bytes
#define TILE_B (128 * ROWB)                 // 10240 bytes per tile
#define STAGE_B (2 * TILE_B)                // A, B = 20480 bytes
#define SMEM_DYN (2 * STAGE_B)              // 40960 bytes -> 2 CTAs/SM

template <int OUT_HALF>
__global__ __launch_bounds__(256, 2)
void gemm_hmma(const __half* __restrict__ A, const __half* __restrict__ B,
               const float* __restrict__ bias, const float* __restrict__ alpha,
               float* __restrict__ outF, __half* __restrict__ outH,
               int M, int N, int K) {
    extern __shared__ char smem[];
    const uint32_t sbase = smem_u32(smem);

    const int tid = threadIdx.x;
    const int wid = tid >> 5, lane = tid & 31;
    const int gid = lane >> 2, tg = lane & 3;
    const int warp_m = (wid & 3) * 32;
    const int warp_n = (wid >> 2) * 64;
    const int block_m = blockIdx.y * 128;
    const int block_n = blockIdx.x * 128;

    uint32_t a_off[2];
#pragma unroll
    for (int mt = 0; mt < 2; mt++)
        a_off[mt] = ((warp_m + mt * 16 + (lane & 15)) * TSTRIDE + (lane >> 4) * 8) * 2;
    uint32_t b_off[4];
#pragma unroll
    for (int nt2 = 0; nt2 < 4; nt2++)
        b_off[nt2] = ((warp_n + nt2 * 16 + (lane >> 4) * 8 + (lane & 7)) * TSTRIDE +
                      ((lane >> 3) & 1) * 8) * 2;

    float acc[2][8][4];
#pragma unroll
    for (int mt = 0; mt < 2; mt++)
#pragma unroll
        for (int nt = 0; nt < 8; nt++)
#pragma unroll
            for (int j = 0; j < 4; j++) acc[mt][nt][j] = 0.f;

    const int nK = K / BK;
    auto stg = [&](int s) { return sbase + (uint32_t)s * STAGE_B; };

    auto load_stage = [&](int ki, int s) {
        const int k0 = ki * BK;
        const uint32_t base = stg(s);
#pragma unroll
        for (int j = 0; j < 2; j++) {
            int chunk = j * 256 + tid;
            int r = chunk >> 2, c = chunk & 3;
            uint32_t so = (uint32_t)(r * ROWB + c * 16);
            cp16(base + so, A + (size_t)(block_m + r) * K + k0 + c * 8);
            cp16(base + TILE_B + so, B + (size_t)(block_n + r) * K + k0 + c * 8);
        }
    };

    load_stage(0, 0);
    CP_COMMIT();

    for (int i = 0; i < nK; i++) {
        CP_WAIT(0);
        __syncthreads();

        if (i + 1 < nK) load_stage(i + 1, (i + 1) & 1);
        CP_COMMIT();

        const uint32_t tA = stg(i & 1);
        const uint32_t tB = tA + TILE_B;

#pragma unroll
        for (int ks = 0; ks < 2; ks++) {
            const uint32_t kb = ks * 32;
            uint32_t af[2][4];
#pragma unroll
            for (int mt = 0; mt < 2; mt++)
                ldsm4(af[mt][0], af[mt][1], af[mt][2], af[mt][3], tA + a_off[mt] + kb);
#pragma unroll
            for (int nt2 = 0; nt2 < 4; nt2++) {
                uint32_t bf[2][2];
                ldsm4(bf[0][0], bf[0][1], bf[1][0], bf[1][1], tB + b_off[nt2] + kb);
#pragma unroll
                for (int h = 0; h < 2; h++) {
                    const int nt = 2 * nt2 + h;
#pragma unroll
                    for (int mt = 0; mt < 2; mt++)
                        mma_f16(acc[mt][nt], af[mt], bf[h]);
                }
            }
        }
    }

    // ---------------- epilogue: bias + PReLU ------------------------------
#pragma unroll
    for (int mt = 0; mt < 2; mt++) {
        const int r0 = block_m + warp_m + mt * 16 + gid;
#pragma unroll
        for (int nt = 0; nt < 8; nt++) {
            const int n = block_n + warp_n + nt * 8 + tg * 2;
            const float b0 = __ldg(&bias[n]),  b1 = __ldg(&bias[n + 1]);
            const float p0 = __ldg(&alpha[n]), p1 = __ldg(&alpha[n + 1]);
#pragma unroll
            for (int half = 0; half < 2; half++) {
                const int r = r0 + half * 8;
                float v0 = acc[mt][nt][half * 2 + 0] + b0;
                float v1 = acc[mt][nt][half * 2 + 1] + b1;
                v0 = v0 >= 0.f ? v0 : p0 * v0;
                v1 = v1 >= 0.f ? v1 : p1 * v1;
                if (OUT_HALF) {
                    __half2 hh;
                    hh.x = __float2half_rn(v0);
                    hh.y = __float2half_rn(v1);
                    *reinterpret_cast<__half2*>(&outH[(size_t)r * N + n]) = hh;
                } else {
                    float2 o; o.x = v0; o.y = v1;
                    *reinterpret_cast<float2*>(&outF[(size_t)r * N + n]) = o;
                }
            }
        }
    }
}

// ------------------------------ launch -------------------------------------
extern "C" void kernel_launch(void* const* d_in, const int* in_sizes, int n_in,
                              void* d_out, int out_size) {
    const float* x       = (const float*)d_in[0];
    const float* weights = (const float*)d_in[1];
    const float* W0 = (const float*)d_in[2];
    const float* b0 = (const float*)d_in[3];
    const float* a0 = (const float*)d_in[4];
    const float* W1 = (const float*)d_in[5];
    const float* b1 = (const float*)d_in[6];
    const float* a1 = (const float*)d_in[7];
    const float* W2 = (const float*)d_in[8];
    const float* b2 = (const float*)d_in[9];
    const float* a2 = (const float*)d_in[10];
    float* out = (float*)d_out;

    auto sym = [](const void* s) {
        void* p = nullptr;
        cudaGetSymbolAddress(&p, (const void*)s);
        return p;
    };
    __half* xh   = (__half*)sym(g_xh);
    __half* act0 = (__half*)sym(g_a0);
    __half* act1 = (__half*)sym(g_a1);
    __half* wt0  = (__half*)sym(g_wt0);
    __half* wt1  = (__half*)sym(g_wt1);
    __half* wt2  = (__half*)sym(g_wt2);
    float* bm0 = (float*)sym(g_bm0);
    float* bm1 = (float*)sym(g_bm1);
    float* bm2 = (float*)sym(g_bm2);

    cudaFuncSetAttribute(gemm_hmma<1>, cudaFuncAttributeMaxDynamicSharedMemorySize, SMEM_DYN);
    cudaFuncSetAttribute(gemm_hmma<0>, cudaFuncAttributeMaxDynamicSharedMemorySize, SMEM_DYN);

    // side stream + events, created once (deterministic work per call)
    static cudaStream_t s1 = nullptr;
    static cudaEvent_t evFork = nullptr, evCast = nullptr, evM0 = nullptr,
                       evM1 = nullptr, evM2 = nullptr, evB = nullptr;
    if (s1 == nullptr) {
        cudaStreamCreateWithFlags(&s1, cudaStreamNonBlocking);
        cudaEventCreateWithFlags(&evFork, cudaEventDisableTiming);
        cudaEventCreateWithFlags(&evCast, cudaEventDisableTiming);
        cudaEventCreateWithFlags(&evM0, cudaEventDisableTiming);
        cudaEventCreateWithFlags(&evM1, cudaEventDisableTiming);
        cudaEventCreateWithFlags(&evM2, cudaEventDisableTiming);
        cudaEventCreateWithFlags(&evB, cudaEventDisableTiming);
    }

    // half-chain pointer offsets (rows 4096..8191)
    const size_t offXH  = (size_t)M_HALF * 512;    // 512-wide fp16 rows
    const size_t offA   = (size_t)M_HALF * 1024;   // 1024-wide fp16 rows
    const size_t offOut = (size_t)M_HALF * 512;    // fp32 out rows

    // grids (half-M chains)
    const dim3 gL0(1024 / 128, M_HALF / 128);      // 256 CTAs
    const dim3 gL1(1024 / 128, M_HALF / 128);      // 256 CTAs
    const dim3 gL2(512 / 128, M_HALF / 128);       // 128 CTAs

    // fork side stream
    cudaEventRecord(evFork, 0);
    cudaStreamWaitEvent(s1, evFork, 0);

    // side stream: cast (all rows), merge1, merge2, then chain B
    cast_x<<<(8192 * 512 / 4 + 255) / 256, 256, 0, s1>>>(
        (const float4*)x, (__half2*)xh, 8192 * 512 / 4);
    cudaEventRecord(evCast, s1);
    merge_w<<<dim3(1024 / 32, 1024 / 32), 256, 0, s1>>>(weights, W1, b1, wt1, bm1, 1024, 1024);
    cudaEventRecord(evM1, s1);
    merge_w<<<dim3(1024 / 32, 512 / 32), 256, 0, s1>>>(weights, W2, b2, wt2, bm2, 1024, 512);
    cudaEventRecord(evM2, s1);

    // main stream: merge0 concurrent with cast
    merge_w<<<dim3(512 / 32, 1024 / 32), 256>>>(weights, W0, b0, wt0, bm0, 512, 1024);
    cudaEventRecord(evM0, 0);

    // ---- chain B (rows 4096..8191) on side stream ----
    // buffers: xh (read-only), act0 (L0 out), act1 (L1 out) — disjoint roles,
    // halves are row-disjoint, so no cross-chain aliasing anywhere.
    cudaStreamWaitEvent(s1, evM0, 0);   // needs merge0 (cast/M1/M2 in-stream)
    gemm_hmma<1><<<gL0, 256, SMEM_DYN, s1>>>(
        xh + offXH, wt0, bm0, a0, nullptr, act0 + offA, M_HALF, 1024, 512);
    gemm_hmma<1><<<gL1, 256, SMEM_DYN, s1>>>(
        act0 + offA, wt1, bm1, a1, nullptr, act1 + offA, M_HALF, 1024, 1024);
    gemm_hmma<0><<<gL2, 256, SMEM_DYN, s1>>>(
        act1 + offA, wt2, bm2, a2, out + offOut, nullptr, M_HALF, 512, 1024);
    cudaEventRecord(evB, s1);

    // ---- chain A (rows 0..4095) on main stream ----
    cudaStreamWaitEvent(0, evCast, 0);
    gemm_hmma<1><<<gL0, 256, SMEM_DYN>>>(
        xh, wt0, bm0, a0, nullptr, act0, M_HALF, 1024, 512);
    cudaStreamWaitEvent(0, evM1, 0);
    gemm_hmma<1><<<gL1, 256, SMEM_DYN>>>(
        act0, wt1, bm1, a1, nullptr, act1, M_HALF, 1024, 1024);
    cudaStreamWaitEvent(0, evM2, 0);
    gemm_hmma<0><<<gL2, 256, SMEM_DYN>>>(
        act1, wt2, bm2, a2, out, nullptr, M_HALF, 512, 1024);

    // join side stream back into the capture-origin stream
    cudaStreamWaitEvent(0, evB, 0);
}

// round 17
// speedup vs baseline: 1.5005x; 1.5005x over previous
#include <cuda_runtime.h>
#include <cuda_fp16.h>
#include <cstdint>

// ===========================================================================
// mie_51281909514553 — 3-layer expert-merged MLP, pure fp16 HMMA
//   wn = weights/sum(weights); per layer: x = PReLU(x @ Wm + bm, a)
//   Weights + activations fp16 (RN), fp32 accumulate (HMMA ceiling:
//   512 MAC/cyc/SM measured). R17: R13 structure (best known, 156.2us;
//   dual-chain/persistent variants empirically regressed) + 3-stage
//   cp.async pipeline (2 chunk-times of load slack), still 2 CTAs/SM.
// ===========================================================================

#define M_ROWS 8192
#define E_EXPERTS 8

// ------------------------------ scratch (no allocs allowed) ----------------
__device__ __half g_xh[8192 * 1024];       // layer input activations (fp16)
__device__ __half g_a0[8192 * 1024];
__device__ __half g_wt0[1024 * 512];       // merged W^T: [N][K] fp16
__device__ __half g_wt1[1024 * 1024];
__device__ __half g_wt2[512 * 1024];
__device__ float g_bm0[1024];
__device__ float g_bm1[1024];
__device__ float g_bm2[512];

// ------------------------------ helpers ------------------------------------
__device__ __forceinline__ uint32_t smem_u32(const void* p) {
    uint32_t a;
    asm("{ .reg .u64 t; cvta.to.shared.u64 t, %1; cvt.u32.u64 %0, t; }"
        : "=r"(a) : "l"(p));
    return a;
}

__device__ __forceinline__ void cp16(uint32_t s, const void* g) {
    asm volatile("cp.async.cg.shared.global [%0], [%1], 16;" :: "r"(s), "l"(g) : "memory");
}
#define CP_COMMIT() asm volatile("cp.async.commit_group;" ::: "memory")
#define CP_WAIT(n)  asm volatile("cp.async.wait_group %0;" :: "n"(n) : "memory")

__device__ __forceinline__ void ldsm4(uint32_t& r0, uint32_t& r1,
                                      uint32_t& r2, uint32_t& r3, uint32_t a) {
    asm volatile("ldmatrix.sync.aligned.m8n8.x4.shared.b16 {%0,%1,%2,%3}, [%4];"
                 : "=r"(r0), "=r"(r1), "=r"(r2), "=r"(r3) : "r"(a));
}

__device__ __forceinline__ void mma_f16(float* c, const uint32_t* a, const uint32_t* b) {
    asm volatile(
        "mma.sync.aligned.m16n8k16.row.col.f32.f16.f16.f32 "
        "{%0,%1,%2,%3}, {%4,%5,%6,%7}, {%8,%9}, {%0,%1,%2,%3};"
        : "+f"(c[0]), "+f"(c[1]), "+f"(c[2]), "+f"(c[3])
        : "r"(a[0]), "r"(a[1]), "r"(a[2]), "r"(a[3]), "r"(b[0]), "r"(b[1]));
}

// ------------------------------ merge+transpose (R13 proven) ---------------
__global__ void merge_w(const float* __restrict__ weights,
                        const float* __restrict__ W,
                        const float* __restrict__ b,
                        __half* __restrict__ T,
                        float* __restrict__ bm,
                        int K, int N) {
    __shared__ float tile[32][33];
    const int tid = threadIdx.x;

    float s = 0.f;
#pragma unroll
    for (int e = 0; e < E_EXPERTS; e++) s += weights[e];
    const float inv = 1.f / s;
    float wn[E_EXPERTS];
#pragma unroll
    for (int e = 0; e < E_EXPERTS; e++) wn[e] = weights[e] * inv;

    const int k0 = blockIdx.x * 32, n0 = blockIdx.y * 32;
    const size_t KN = (size_t)K * N;

    {
        const int kk = tid >> 3;
        const int v = tid & 7;
        const float* src = W + (size_t)(k0 + kk) * N + n0 + v * 4;
        float4 acc = make_float4(0.f, 0.f, 0.f, 0.f);
#pragma unroll
        for (int e = 0; e < E_EXPERTS; e++) {
            float4 w4 = *reinterpret_cast<const float4*>(src + (size_t)e * KN);
            acc.x = fmaf(wn[e], w4.x, acc.x);
            acc.y = fmaf(wn[e], w4.y, acc.y);
            acc.z = fmaf(wn[e], w4.z, acc.z);
            acc.w = fmaf(wn[e], w4.w, acc.w);
        }
        tile[kk][v * 4 + 0] = acc.x;
        tile[kk][v * 4 + 1] = acc.y;
        tile[kk][v * 4 + 2] = acc.z;
        tile[kk][v * 4 + 3] = acc.w;
    }

    if (blockIdx.x == 0 && tid < 32) {
        const int n = n0 + tid;
        float acc = 0.f;
#pragma unroll
        for (int e = 0; e < E_EXPERTS; e++) acc += wn[e] * b[e * N + n];
        bm[n] = acc;
    }
    __syncthreads();

    {
        const int tx = tid & 31;
        for (int ty = tid >> 5; ty < 32; ty += 8)
            T[(size_t)(n0 + ty) * K + k0 + tx] = __float2half_rn(tile[tx][ty]);
    }
}

// fp32 -> fp16, vectorized (float4 in, half2x2 out)
__global__ void cast_x(const float4* __restrict__ x, __half2* __restrict__ xh, int n4) {
    int i = blockIdx.x * blockDim.x + threadIdx.x;
    if (i < n4) {
        float4 v = x[i];
        __half2 a, b;
        a.x = __float2half_rn(v.x); a.y = __float2half_rn(v.y);
        b.x = __float2half_rn(v.z); b.y = __float2half_rn(v.w);
        xh[2 * i] = a;
        xh[2 * i + 1] = b;
    }
}

// ------------------------------ HMMA GEMM ----------------------------------
// BM=128, BN=128, BK=32, 256 threads (8 warps: 4 M x 2 N), warp tile 32x64.
// 3-stage cp.async pipeline, one sync per chunk, 2 CTAs per SM.
#define BK 32
#define STAGES 3
#define TSTRIDE 40
#define ROWB (TSTRIDE * 2)                  // 80 bytes
#define TILE_B (128 * ROWB)                 // 10240 bytes per tile
#define STAGE_B (2 * TILE_B)                // A, B = 20480 bytes
#define SMEM_DYN (STAGES * STAGE_B)         // 61440 bytes -> 2 CTAs/SM (122.9KB)

template <int OUT_HALF>
__global__ __launch_bounds__(256, 2)
void gemm_hmma(const __half* __restrict__ A, const __half* __restrict__ B,
               const float* __restrict__ bias, const float* __restrict__ alpha,
               float* __restrict__ outF, __half* __restrict__ outH,
               int M, int N, int K) {
    extern __shared__ char smem[];
    const uint32_t sbase = smem_u32(smem);

    const int tid = threadIdx.x;
    const int wid = tid >> 5, lane = tid & 31;
    const int gid = lane >> 2, tg = lane & 3;
    const int warp_m = (wid & 3) * 32;
    const int warp_n = (wid >> 2) * 64;
    const int block_m = blockIdx.y * 128;
    const int block_n = blockIdx.x * 128;

    uint32_t a_off[2];
#pragma unroll
    for (int mt = 0; mt < 2; mt++)
        a_off[mt] = ((warp_m + mt * 16 + (lane & 15)) * TSTRIDE + (lane >> 4) * 8) * 2;
    uint32_t b_off[4];
#pragma unroll
    for (int nt2 = 0; nt2 < 4; nt2++)
        b_off[nt2] = ((warp_n + nt2 * 16 + (lane >> 4) * 8 + (lane & 7)) * TSTRIDE +
                      ((lane >> 3) & 1) * 8) * 2;

    float acc[2][8][4];
#pragma unroll
    for (int mt = 0; mt < 2; mt++)
#pragma unroll
        for (int nt = 0; nt < 8; nt++)
#pragma unroll
            for (int j = 0; j < 4; j++) acc[mt][nt][j] = 0.f;

    const int nK = K / BK;
    auto stg = [&](int s) { return sbase + (uint32_t)s * STAGE_B; };

    auto load_stage = [&](int ki, int s) {
        const int k0 = ki * BK;
        const uint32_t base = stg(s);
#pragma unroll
        for (int j = 0; j < 2; j++) {
            int chunk = j * 256 + tid;
            int r = chunk >> 2, c = chunk & 3;
            uint32_t so = (uint32_t)(r * ROWB + c * 16);
            cp16(base + so, A + (size_t)(block_m + r) * K + k0 + c * 8);
            cp16(base + TILE_B + so, B + (size_t)(block_n + r) * K + k0 + c * 8);
        }
    };

    // preload chunks 0, 1
    load_stage(0, 0);
    CP_COMMIT();
    if (nK > 1) load_stage(1, 1);
    CP_COMMIT();

    for (int i = 0; i < nK; i++) {
        CP_WAIT(1);                 // chunk i resident (i+1 may be in flight)
        __syncthreads();            // all warps done with chunk i-1's slot

        // prefetch chunk i+2 into slot freed by chunk i-1
        if (i + 2 < nK) load_stage(i + 2, (i + 2) % STAGES);
        CP_COMMIT();

        const uint32_t tA = stg(i % STAGES);
        const uint32_t tB = tA + TILE_B;

#pragma unroll
        for (int ks = 0; ks < 2; ks++) {
            const uint32_t kb = ks * 32;
            uint32_t af[2][4];
#pragma unroll
            for (int mt = 0; mt < 2; mt++)
                ldsm4(af[mt][0], af[mt][1], af[mt][2], af[mt][3], tA + a_off[mt] + kb);
#pragma unroll
            for (int nt2 = 0; nt2 < 4; nt2++) {
                uint32_t bf[2][2];
                ldsm4(bf[0][0], bf[0][1], bf[1][0], bf[1][1], tB + b_off[nt2] + kb);
#pragma unroll
                for (int h = 0; h < 2; h++) {
                    const int nt = 2 * nt2 + h;
#pragma unroll
                    for (int mt = 0; mt < 2; mt++)
                        mma_f16(acc[mt][nt], af[mt], bf[h]);
                }
            }
        }
    }

    // ---------------- epilogue: bias + PReLU ------------------------------
#pragma unroll
    for (int mt = 0; mt < 2; mt++) {
        const int r0 = block_m + warp_m + mt * 16 + gid;
#pragma unroll
        for (int nt = 0; nt < 8; nt++) {
            const int n = block_n + warp_n + nt * 8 + tg * 2;
            const float b0 = __ldg(&bias[n]),  b1 = __ldg(&bias[n + 1]);
            const float p0 = __ldg(&alpha[n]), p1 = __ldg(&alpha[n + 1]);
#pragma unroll
            for (int half = 0; half < 2; half++) {
                const int r = r0 + half * 8;
                float v0 = acc[mt][nt][half * 2 + 0] + b0;
                float v1 = acc[mt][nt][half * 2 + 1] + b1;
                v0 = v0 >= 0.f ? v0 : p0 * v0;
                v1 = v1 >= 0.f ? v1 : p1 * v1;
                if (OUT_HALF) {
                    __half2 hh;
                    hh.x = __float2half_rn(v0);
                    hh.y = __float2half_rn(v1);
                    *reinterpret_cast<__half2*>(&outH[(size_t)r * N + n]) = hh;
                } else {
                    float2 o; o.x = v0; o.y = v1;
                    *reinterpret_cast<float2*>(&outF[(size_t)r * N + n]) = o;
                }
            }
        }
    }
}

// ------------------------------ launch -------------------------------------
extern "C" void kernel_launch(void* const* d_in, const int* in_sizes, int n_in,
                              void* d_out, int out_size) {
    const float* x       = (const float*)d_in[0];
    const float* weights = (const float*)d_in[1];
    const float* W0 = (const float*)d_in[2];
    const float* b0 = (const float*)d_in[3];
    const float* a0 = (const float*)d_in[4];
    const float* W1 = (const float*)d_in[5];
    const float* b1 = (const float*)d_in[6];
    const float* a1 = (const float*)d_in[7];
    const float* W2 = (const float*)d_in[8];
    const float* b2 = (const float*)d_in[9];
    const float* a2 = (const float*)d_in[10];
    float* out = (float*)d_out;

    auto sym = [](const void* s) {
        void* p = nullptr;
        cudaGetSymbolAddress(&p, (const void*)s);
        return p;
    };
    __half* xh   = (__half*)sym(g_xh);
    __half* act0 = (__half*)sym(g_a0);
    __half* wt0  = (__half*)sym(g_wt0);
    __half* wt1  = (__half*)sym(g_wt1);
    __half* wt2  = (__half*)sym(g_wt2);
    float* bm0 = (float*)sym(g_bm0);
    float* bm1 = (float*)sym(g_bm1);
    float* bm2 = (float*)sym(g_bm2);

    cudaFuncSetAttribute(gemm_hmma<1>, cudaFuncAttributeMaxDynamicSharedMemorySize, SMEM_DYN);
    cudaFuncSetAttribute(gemm_hmma<0>, cudaFuncAttributeMaxDynamicSharedMemorySize, SMEM_DYN);

    // side stream + events, created once (deterministic work per call)
    static cudaStream_t s1 = nullptr;
    static cudaEvent_t evFork = nullptr, evCast = nullptr, evM1 = nullptr, evM2 = nullptr;
    if (s1 == nullptr) {
        cudaStreamCreateWithFlags(&s1, cudaStreamNonBlocking);
        cudaEventCreateWithFlags(&evFork, cudaEventDisableTiming);
        cudaEventCreateWithFlags(&evCast, cudaEventDisableTiming);
        cudaEventCreateWithFlags(&evM1, cudaEventDisableTiming);
        cudaEventCreateWithFlags(&evM2, cudaEventDisableTiming);
    }

    // fork side stream off the main stream's current front
    cudaEventRecord(evFork, 0);
    cudaStreamWaitEvent(s1, evFork, 0);

    // side stream: cast (only needs x) runs concurrent with merge0 on main;
    // then merges for layers 1, 2 overlap gemm0/gemm1.
    cast_x<<<(8192 * 512 / 4 + 255) / 256, 256, 0, s1>>>(
        (const float4*)x, (__half2*)xh, 8192 * 512 / 4);
    cudaEventRecord(evCast, s1);
    merge_w<<<dim3(1024 / 32, 1024 / 32), 256, 0, s1>>>(weights, W1, b1, wt1, bm1, 1024, 1024);
    cudaEventRecord(evM1, s1);
    merge_w<<<dim3(1024 / 32, 512 / 32), 256, 0, s1>>>(weights, W2, b2, wt2, bm2, 1024, 512);
    cudaEventRecord(evM2, s1);

    // main stream: merge0 concurrent with cast
    merge_w<<<dim3(512 / 32, 1024 / 32), 256>>>(weights, W0, b0, wt0, bm0, 512, 1024);

    // layer 0 (needs merge0 + cast)
    cudaStreamWaitEvent(0, evCast, 0);
    gemm_hmma<1><<<dim3(1024 / 128, M_ROWS / 128), 256, SMEM_DYN>>>(
        xh, wt0, bm0, a0, nullptr, act0, M_ROWS, 1024, 512);

    // layer 1 (needs merge1)
    cudaStreamWaitEvent(0, evM1, 0);
    gemm_hmma<1><<<dim3(1024 / 128, M_ROWS / 128), 256, SMEM_DYN>>>(
        act0, wt1, bm1, a1, nullptr, xh, M_ROWS, 1024, 1024);

    // layer 2 (needs merge2) -> fp32 out; joins side stream back into main
    cudaStreamWaitEvent(0, evM2, 0);
    gemm_hmma<0><<<dim3(512 / 128, M_ROWS / 128), 256, SMEM_DYN>>>(
        xh, wt2, bm2, a2, out, nullptr, M_ROWS, 512, 1024);
}